// round 13
// baseline (speedup 1.0000x reference)
#include <cuda_runtime.h>

#define NN   20000
#define EE   320000
#define DIND 128
#define DH   64
#define H    8
#define B    16
#define C    10
#define NB79 ((NN + 255) / 256)
#define CAP2 64

// ---------------- packed f32x2 helpers ----------------------------------------
__device__ __forceinline__ unsigned long long pack2(float x, float y) {
    unsigned long long u;
    asm("mov.b64 %0, {%1,%2};" : "=l"(u) : "f"(x), "f"(y));
    return u;
}
__device__ __forceinline__ void unpack2(unsigned long long u, float& x, float& y) {
    asm("mov.b64 {%0,%1}, %2;" : "=f"(x), "=f"(y) : "l"(u));
}
__device__ __forceinline__ unsigned long long fma2(unsigned long long a,
                                                   unsigned long long b,
                                                   unsigned long long c) {
    unsigned long long d;
    asm("fma.rn.f32x2 %0, %1, %2, %3;" : "=l"(d) : "l"(a), "l"(b), "l"(c));
    return d;
}

// ---------------- scratch (static device globals; zero-init at load) -----------
__device__ float d_h0[NN * DH];
__device__ float d_agg[NN * H * DH];   // layer-0 aggregates only
__device__ float d_el[NN * H];         // layer-1 logits (k_in)
__device__ float d_er[NN * H];
__device__ float d_el2[NN * H];        // layer-2 logits (k_post)
__device__ float d_er2[NN * H];
__device__ float d_hmid[NN * DH];
__device__ float d_wl1[H * DH], d_wr1[H * DH], d_wl2[H * DH], d_wr2[H * DH];
__device__ int   d_deg[NN];            // zeroed by k_agg2_l1 of previous replay
__device__ int   d_rowptr[NN + 1];
__device__ int   d_wpos[NN];           // (re)written by k_addoff2 every replay
__device__ int   d_col[EE];
__device__ int   d_part[NB79];
__device__ float d_gsum2[B * 512];     // per-graph agg sums; zeroed by k_head
__device__ float d_gcnt[B];            // zeroed by k_head

// ---------------- histogram of incoming degree ----------------------------------
__global__ void k_hist(const int* __restrict__ edst) {
    int e = blockIdx.x * 256 + threadIdx.x;
    if (e < EE) atomicAdd(&d_deg[edst[e]], 1);
}

// ---------------- fold attn vectors through W (single block, side stream) ------
__global__ void k_fold(const float* __restrict__ W1, const float* __restrict__ al1,
                       const float* __restrict__ ar1,
                       const float* __restrict__ W2, const float* __restrict__ al2,
                       const float* __restrict__ ar2) {
    int t = threadIdx.x;
    int h = t >> 6, k = t & 63;
    float l1 = 0.f, r1 = 0.f, l2 = 0.f, r2 = 0.f;
    for (int d = 0; d < DH; d++) {
        float w1 = W1[k * 512 + h * 64 + d];
        float w2 = W2[k * 512 + h * 64 + d];
        l1 += w1 * al1[h * 64 + d];
        r1 += w1 * ar1[h * 64 + d];
        l2 += w2 * al2[h * 64 + d];
        r2 += w2 * ar2[h * 64 + d];
    }
    d_wl1[t] = l1; d_wr1[t] = r1;
    d_wl2[t] = l2; d_wr2[t] = r2;
}

__global__ void k_part() {
    __shared__ int ws[8];
    int i = blockIdx.x * 256 + threadIdx.x;
    int v = (i < NN) ? d_deg[i] : 0;
#pragma unroll
    for (int o = 16; o; o >>= 1) v += __shfl_xor_sync(0xffffffffu, v, o);
    if ((threadIdx.x & 31) == 0) ws[threadIdx.x >> 5] = v;
    __syncthreads();
    if (threadIdx.x == 0) {
        int s = 0;
#pragma unroll
        for (int w = 0; w < 8; w++) s += ws[w];
        d_part[blockIdx.x] = s;
    }
}

// rowptr + row-start (into wpos); partial-scan of 79 block sums per block
__global__ void k_addoff2() {
    __shared__ int parts[NB79];
    __shared__ int ws[8];
    int t = threadIdx.x;
    int lane = t & 31, wid = t >> 5;
    if (t < NB79) parts[t] = d_part[t];
    __syncthreads();
    if (t == 0) {
        int run = 0;
        for (int i = 0; i < NB79; i++) { int v = parts[i]; parts[i] = run; run += v; }
    }
    __syncthreads();
    int i = blockIdx.x * 256 + t;
    int v0 = (i < NN) ? d_deg[i] : 0;
    int v = v0;
#pragma unroll
    for (int o = 1; o < 32; o <<= 1) {
        int x = __shfl_up_sync(0xffffffffu, v, o);
        if (lane >= o) v += x;
    }
    if (lane == 31) ws[wid] = v;
    __syncthreads();
    int woff = 0;
#pragma unroll
    for (int w = 0; w < 8; w++) woff += (w < wid) ? ws[w] : 0;
    if (i < NN) {
        int endp = parts[blockIdx.x] + woff + v;
        d_rowptr[i + 1] = endp;
        d_wpos[i] = endp - v0;
    }
    if (i == 0) d_rowptr[0] = 0;
}

__global__ void k_scatter(const int* __restrict__ esrc, const int* __restrict__ edst) {
    int e = blockIdx.x * 256 + threadIdx.x;
    if (e < EE) {
        int p = atomicAdd(&d_wpos[edst[e]], 1);
        d_col[p] = esrc[e];
    }
}

// ------- h0 = g@W_in + b (16 nodes, 128 threads) + fused layer-1 el/er ---------
__global__ __launch_bounds__(128) void k_in(const float* __restrict__ g,
                                            const float* __restrict__ W,
                                            const float* __restrict__ b) {
    __shared__ float sh_t[DIND * 20];
    __shared__ float s_h[16 * 68];
    __shared__ float s_w[2 * 544];
    int n0 = blockIdx.x * 16;
    int t = threadIdx.x;
#pragma unroll
    for (int r = 0; r < 4; r++) {
        int idx = t + 128 * r;
        int h = idx >> 6, d = idx & 63;
        s_w[h * 68 + d]       = d_wl1[idx];
        s_w[544 + h * 68 + d] = d_wr1[idx];
    }
#pragma unroll
    for (int r = 0; r < 16; r++) {
        int idx = t + 128 * r;
        int i = idx >> 7, k = idx & 127;
        sh_t[k * 20 + i] = g[(size_t)(n0 + i) * DIND + k];
    }
    __syncthreads();
    int col = t & 63, grp = t >> 6;
    unsigned long long acc[4] = {0ull, 0ull, 0ull, 0ull};
    for (int k = 0; k < DIND; k++) {
        float w = W[k * DH + col];
        unsigned long long ww = pack2(w, w);
        const ulonglong2* p = (const ulonglong2*)&sh_t[k * 20 + 8 * grp];
        ulonglong2 v0 = p[0], v1 = p[1];
        acc[0] = fma2(v0.x, ww, acc[0]);
        acc[1] = fma2(v0.y, ww, acc[1]);
        acc[2] = fma2(v1.x, ww, acc[2]);
        acc[3] = fma2(v1.y, ww, acc[3]);
    }
    float bb = b[col];
#pragma unroll
    for (int j = 0; j < 4; j++) {
        float x, y;
        unpack2(acc[j], x, y);
        x += bb; y += bb;
        int nd = 8 * grp + 2 * j;
        d_h0[(size_t)(n0 + nd) * DH + col]     = x;
        d_h0[(size_t)(n0 + nd + 1) * DH + col] = y;
        s_h[nd * 68 + col]       = x;
        s_h[(nd + 1) * 68 + col] = y;
    }
    __syncthreads();
    {
        int n = t >> 3, h = t & 7;
        const float4* sh4 = (const float4*)(s_h + n * 68);
        const float4* wl4 = (const float4*)(s_w + h * 68);
        const float4* wr4 = (const float4*)(s_w + 544 + h * 68);
        float el = 0.f, er = 0.f;
#pragma unroll
        for (int dd = 0; dd < 16; dd++) {
            float4 hv = sh4[dd];
            float4 a = wl4[dd];
            float4 r = wr4[dd];
            el += hv.x * a.x + hv.y * a.y + hv.z * a.z + hv.w * a.w;
            er += hv.x * r.x + hv.y * r.y + hv.z * r.z + hv.w * r.w;
        }
        d_el[(n0 + n) * 8 + h] = el;
        d_er[(n0 + n) * 8 + h] = er;
    }
}

// ===== shared body: softmax + 8-head gather; acc returned in registers =========
__device__ __forceinline__ void agg_body(
    const float* __restrict__ hin, const float* __restrict__ elp,
    const float* __restrict__ erp,
    float (*s_alpha)[CAP2][8], int (*s_col)[CAP2],
    float (*s_m)[8], float (*s_inv)[8], float (*s_er)[8],
    int w, int lane, int n, int base, int deg, int dcap,
    unsigned long long acc[8]) {
    for (int k = lane; k < dcap; k += 32) s_col[w][k] = d_col[base + k];
    __syncwarp();

    int h = lane & 7, slot8 = lane >> 3;
    float er_h = erp[n * 8 + h];
#pragma unroll 4
    for (int k = slot8; k < dcap; k += 4) {
        int s = s_col[w][k];
        float e = elp[s * 8 + h] + er_h;
        e = e > 0.f ? e : 0.2f * e;
        s_alpha[w][k][h] = e;
    }
    float mo = -1e30f, sso = 0.f;                // overflow region (rare)
    for (int k = CAP2 + slot8; k < deg; k += 4) {
        int s = d_col[base + k];
        float e = elp[s * 8 + h] + er_h;
        e = e > 0.f ? e : 0.2f * e;
        float nm = fmaxf(mo, e);
        sso = sso * __expf(mo - nm) + __expf(e - nm);
        mo = nm;
    }
    __syncwarp();

    float m = mo;
    for (int k = slot8; k < dcap; k += 4) m = fmaxf(m, s_alpha[w][k][h]);
#pragma unroll
    for (int o = 8; o <= 16; o <<= 1) m = fmaxf(m, __shfl_xor_sync(0xffffffffu, m, o));
    float ss = sso * __expf(mo - m);
    for (int k = slot8; k < dcap; k += 4) ss += __expf(s_alpha[w][k][h] - m);
#pragma unroll
    for (int o = 8; o <= 16; o <<= 1) ss += __shfl_xor_sync(0xffffffffu, ss, o);
    float inv = 1.f / ss;
    if (lane < 8) { s_m[w][h] = m; s_inv[w][h] = inv; s_er[w][h] = er_h; }

    for (int k = slot8; k < dcap; k += 4)
        s_alpha[w][k][h] = __expf(s_alpha[w][k][h] - m) * inv;
    __syncwarp();

#pragma unroll
    for (int j = 0; j < 8; j++) acc[j] = 0ull;
    const float* hb = hin + 2 * lane;
#pragma unroll 4
    for (int k = 0; k < dcap; k++) {
        int s = s_col[w][k];
        unsigned long long f = *(const unsigned long long*)(hb + (size_t)s * 64);
        const float4* ap = (const float4*)&s_alpha[w][k][0];
        float4 a0 = ap[0], a1 = ap[1];
        acc[0] = fma2(f, pack2(a0.x, a0.x), acc[0]);
        acc[1] = fma2(f, pack2(a0.y, a0.y), acc[1]);
        acc[2] = fma2(f, pack2(a0.z, a0.z), acc[2]);
        acc[3] = fma2(f, pack2(a0.w, a0.w), acc[3]);
        acc[4] = fma2(f, pack2(a1.x, a1.x), acc[4]);
        acc[5] = fma2(f, pack2(a1.y, a1.y), acc[5]);
        acc[6] = fma2(f, pack2(a1.z, a1.z), acc[6]);
        acc[7] = fma2(f, pack2(a1.w, a1.w), acc[7]);
    }
    if (deg > CAP2) {
        for (int k = CAP2; k < deg; k++) {
            int s = d_col[base + k];
            unsigned long long f = *(const unsigned long long*)(hb + (size_t)s * 64);
#pragma unroll
            for (int hh = 0; hh < 8; hh++) {
                float e = elp[s * 8 + hh] + s_er[w][hh];
                e = e > 0.f ? e : 0.2f * e;
                float a = __expf(e - s_m[w][hh]) * s_inv[w][hh];
                acc[hh] = fma2(f, pack2(a, a), acc[hh]);
            }
        }
    }
}

// ------- layer-0 aggregation: write per-node aggregate to d_agg ----------------
__global__ __launch_bounds__(256) void k_agg2_l0() {
    __shared__ float s_alpha[8][CAP2][8];
    __shared__ int   s_col[8][CAP2];
    __shared__ float s_m[8][8], s_inv[8][8], s_er[8][8];
    int w = threadIdx.x >> 5, lane = threadIdx.x & 31;
    int n = blockIdx.x * 8 + w;
    int base = d_rowptr[n];
    int deg  = d_rowptr[n + 1] - base;
    int dcap = min(deg, CAP2);
    unsigned long long acc[8];
    agg_body(d_h0, d_el, d_er, s_alpha, s_col, s_m, s_inv, s_er,
             w, lane, n, base, deg, dcap, acc);
    float* ob = d_agg + (size_t)n * 512 + 2 * lane;
#pragma unroll
    for (int hh = 0; hh < 8; hh++)
        *(unsigned long long*)(ob + hh * 64) = acc[hh];
}

// ------- layer-1 aggregation + per-graph reduction (atomic-free smem) ----------
__global__ __launch_bounds__(256) void k_agg2_l1(const int* __restrict__ gid) {
    __shared__ float s_alpha[8][CAP2][8];      // 4096 floats; reused as accum
    __shared__ int   s_col[8][CAP2];
    __shared__ float s_m[8][8], s_inv[8][8], s_er[8][8];
    __shared__ int   s_gid[8];
    float* accum = &s_alpha[0][0][0];
    int t = threadIdx.x;
    int w = t >> 5, lane = t & 31;
    int n = blockIdx.x * 8 + w;
    int base = d_rowptr[n];
    int deg  = d_rowptr[n + 1] - base;
    int dcap = min(deg, CAP2);
    unsigned long long acc[8];
    agg_body(d_hmid, d_el2, d_er2, s_alpha, s_col, s_m, s_inv, s_er,
             w, lane, n, base, deg, dcap, acc);

    __syncthreads();                              // everyone done with s_alpha
    // warp w plain-stores its 512-float aggregate into its own region
#pragma unroll
    for (int hh = 0; hh < 8; hh++)
        *(unsigned long long*)&accum[w * 512 + hh * 64 + 2 * lane] = acc[hh];
    if (t < 8) {
        s_gid[t] = gid[blockIdx.x * 8 + t];
        atomicAdd(&d_gcnt[s_gid[t]], 1.f);
        d_deg[blockIdx.x * 8 + t] = 0;            // clean for replay
    }
    __syncthreads();
    int gfirst = s_gid[0], glast = s_gid[7];
    if (gfirst == glast) {                        // common case: one graph
#pragma unroll
        for (int q = 0; q < 2; q++) {
            int d = t + 256 * q;
            float s = 0.f;
#pragma unroll
            for (int ww = 0; ww < 8; ww++) s += accum[ww * 512 + d];
            atomicAdd(&d_gsum2[gfirst * 512 + d], s);
        }
    } else {                                      // boundary block: <=8 graphs
#pragma unroll
        for (int q = 0; q < 2; q++) {
            int d = t + 256 * q;
            for (int gg = gfirst; gg <= glast; gg++) {
                float s = 0.f;
                bool any = false;
#pragma unroll
                for (int ww = 0; ww < 8; ww++)
                    if (s_gid[ww] == gg) { s += accum[ww * 512 + d]; any = true; }
                if (any) atomicAdd(&d_gsum2[gg * 512 + d], s);
            }
        }
    }
}

// ------- post (layer 0 only): per-head GEMM + bias + relu + head-mean ----------
// + fused layer-2 el/er. thread = 4 cols x 16 nodes.
__global__ __launch_bounds__(256, 2) void k_post(const float* __restrict__ W,
                                                 const float* __restrict__ bias) {
    extern __shared__ float sm[];
    float* aggT = sm;                           // [512][36] staging, later [32][512]
    float* s_h  = sm + 512 * 36;                // [32][68]
    float* s_w  = s_h + 32 * 68;                // wl2|wr2 (rows padded to 68)
    int n0 = blockIdx.x * 32;
    int t = threadIdx.x;
    {
        int h = t >> 6, d = t & 63;
        s_w[h * 68 + d]           = d_wl2[t];
        s_w[544 + h * 68 + d]     = d_wr2[t];
        int t2 = t + 256, h2 = t2 >> 6, d2 = t2 & 63;
        s_w[h2 * 68 + d2]         = d_wl2[t2];
        s_w[544 + h2 * 68 + d2]   = d_wr2[t2];
    }
#pragma unroll
    for (int r = 0; r < 64; r++) {
        int idx = t + 256 * r;                   // 16384 elements
        int i = idx >> 9, j = idx & 511;
        aggT[j * 36 + i] = d_agg[(size_t)(n0 + i) * 512 + j];
    }
    __syncthreads();
    int cg = t & 127, half = t >> 7;             // cols 4cg..4cg+3; nodes 16half..+15
    int h = cg >> 4;
    int colb = 4 * cg;
    unsigned long long acc[32];
#pragma unroll
    for (int j = 0; j < 32; j++) acc[j] = 0ull;
    const float4* W4 = (const float4*)W;
    for (int k = 0; k < DH; k++) {
        float4 wv = W4[k * 128 + cg];
        unsigned long long ww0 = pack2(wv.x, wv.x);
        unsigned long long ww1 = pack2(wv.y, wv.y);
        unsigned long long ww2 = pack2(wv.z, wv.z);
        unsigned long long ww3 = pack2(wv.w, wv.w);
        const ulonglong2* p = (const ulonglong2*)&aggT[(h * 64 + k) * 36 + 16 * half];
#pragma unroll
        for (int j = 0; j < 4; j++) {
            ulonglong2 v = p[j];
            acc[(2 * j) * 4 + 0]     = fma2(v.x, ww0, acc[(2 * j) * 4 + 0]);
            acc[(2 * j) * 4 + 1]     = fma2(v.x, ww1, acc[(2 * j) * 4 + 1]);
            acc[(2 * j) * 4 + 2]     = fma2(v.x, ww2, acc[(2 * j) * 4 + 2]);
            acc[(2 * j) * 4 + 3]     = fma2(v.x, ww3, acc[(2 * j) * 4 + 3]);
            acc[(2 * j + 1) * 4 + 0] = fma2(v.y, ww0, acc[(2 * j + 1) * 4 + 0]);
            acc[(2 * j + 1) * 4 + 1] = fma2(v.y, ww1, acc[(2 * j + 1) * 4 + 1]);
            acc[(2 * j + 1) * 4 + 2] = fma2(v.y, ww2, acc[(2 * j + 1) * 4 + 2]);
            acc[(2 * j + 1) * 4 + 3] = fma2(v.y, ww3, acc[(2 * j + 1) * 4 + 3]);
        }
    }
    __syncthreads();                             // aggT reused as output buffer
    float4 bb = ((const float4*)bias)[cg];
#pragma unroll
    for (int q = 0; q < 8; q++) {
        float x0, y0, x1, y1, x2, y2, x3, y3;
        unpack2(acc[q * 4 + 0], x0, y0);
        unpack2(acc[q * 4 + 1], x1, y1);
        unpack2(acc[q * 4 + 2], x2, y2);
        unpack2(acc[q * 4 + 3], x3, y3);
        int node = 16 * half + 2 * q;
        float4 vx = make_float4(x0 + bb.x, x1 + bb.y, x2 + bb.z, x3 + bb.w);
        float4 vy = make_float4(y0 + bb.x, y1 + bb.y, y2 + bb.z, y3 + bb.w);
        *(float4*)&aggT[node * 512 + colb]       = vx;
        *(float4*)&aggT[(node + 1) * 512 + colb] = vy;
    }
    __syncthreads();
#pragma unroll
    for (int r = 0; r < 8; r++) {
        int idx = t + 256 * r;                   // 2048 = 32 nodes x 64 dims
        int i = idx >> 6, d = idx & 63;
        float v = 0.f;
#pragma unroll
        for (int hh = 0; hh < 8; hh++) v += aggT[i * 512 + hh * 64 + d];
        v = fmaxf(v * 0.125f, 0.f);
        d_hmid[(size_t)(n0 + i) * DH + d] = v;
        s_h[i * 68 + d] = v;
    }
    __syncthreads();
    {                                            // 32 nodes x 8 heads = 256 threads
        int nn = t >> 3, h2 = t & 7;
        const float4* sh4 = (const float4*)(s_h + nn * 68);
        const float4* wl4 = (const float4*)(s_w + h2 * 68);
        const float4* wr4 = (const float4*)(s_w + 544 + h2 * 68);
        float el = 0.f, er = 0.f;
#pragma unroll
        for (int dd = 0; dd < 16; dd++) {
            float4 hv = sh4[dd];
            float4 a = wl4[dd];
            float4 r = wr4[dd];
            el += hv.x * a.x + hv.y * a.y + hv.z * a.z + hv.w * a.w;
            er += hv.x * r.x + hv.y * r.y + hv.z * r.z + hv.w * r.w;
        }
        d_el2[(n0 + nn) * 8 + h2] = el;
        d_er2[(n0 + nn) * 8 + h2] = er;
    }
}

// ------- head: graph-level GEMM (folded layer-2 linear) + classifier + softmax --
__global__ __launch_bounds__(512) void k_head(const float* __restrict__ W2,
                                              const float* __restrict__ bias2,
                                              const float* __restrict__ Wh,
                                              const float* __restrict__ bh,
                                              float* __restrict__ out) {
    __shared__ float s_g[B * 512];
    __shared__ float s_hg[B * 64];
    __shared__ float s_cnt[B];
    __shared__ float lg[B][C];
    int t = threadIdx.x;
    for (int i = t; i < B * 512; i += 512) s_g[i] = d_gsum2[i];
    if (t < B) s_cnt[t] = d_gcnt[t];
    __syncthreads();
#pragma unroll
    for (int q = 0; q < 2; q++) {
        int idx = t + 512 * q;                   // 1024 = 16 graphs x 64 dims
        int g = idx >> 6, d = idx & 63;
        float acc = 0.f;
#pragma unroll
        for (int h = 0; h < 8; h++) {
            const float* wcol = W2 + h * 64 + d;
            const float* gv = s_g + g * 512 + h * 64;
#pragma unroll 16
            for (int k = 0; k < 64; k++)
                acc += gv[k] * wcol[k * 512];
        }
        float bm = 0.f;
#pragma unroll
        for (int h = 0; h < 8; h++) bm += bias2[h * 64 + d];
        float cnt = s_cnt[g];
        s_hg[idx] = (cnt > 0.f) ? (acc / (8.f * cnt) + bm * 0.125f) : 0.f;
    }
    __syncthreads();
    if (t < B * C) {
        int b = t / C, c = t % C;
        float a = 0.f;
#pragma unroll
        for (int d = 0; d < DH; d++) a += s_hg[b * 64 + d] * Wh[d * C + c];
        lg[b][c] = a + bh[c];
    }
    __syncthreads();
    if (t < B) {
        float mx = -1e30f;
        for (int c = 0; c < C; c++) mx = fmaxf(mx, lg[t][c]);
        float s = 0.f;
        for (int c = 0; c < C; c++) { float e = expf(lg[t][c] - mx); lg[t][c] = e; s += e; }
        for (int c = 0; c < C; c++) out[t * C + c] = lg[t][c] / s;
    }
    __syncthreads();
    for (int i = t; i < B * 512; i += 512) d_gsum2[i] = 0.f;   // clean for replay
    if (t < B) d_gcnt[t] = 0.f;
}

// ---------------- launch (two-stream fork: CSR build || input GEMM) ------------
extern "C" void kernel_launch(void* const* d_in, const int* in_sizes, int n_in,
                              void* d_out, int out_size) {
    const float* g    = (const float*)d_in[0];
    const int*   esrc = (const int*)d_in[1];
    const int*   edst = (const int*)d_in[2];
    const int*   gid  = (const int*)d_in[3];
    const float* W_in = (const float*)d_in[4];
    const float* b_in = (const float*)d_in[5];
    const float* W1   = (const float*)d_in[6];
    const float* al1  = (const float*)d_in[7];
    const float* ar1  = (const float*)d_in[8];
    const float* bias1= (const float*)d_in[9];
    const float* W2   = (const float*)d_in[10];
    const float* al2  = (const float*)d_in[11];
    const float* ar2  = (const float*)d_in[12];
    const float* bias2= (const float*)d_in[13];
    const float* Wh   = (const float*)d_in[14];
    const float* bh   = (const float*)d_in[15];
    float* out = (float*)d_out;

    static cudaStream_t s2 = nullptr;
    static cudaEvent_t evFork = nullptr, evJoin = nullptr;
    if (s2 == nullptr) {
        cudaStreamCreateWithFlags(&s2, cudaStreamNonBlocking);
        cudaEventCreateWithFlags(&evFork, cudaEventDisableTiming);
        cudaEventCreateWithFlags(&evJoin, cudaEventDisableTiming);
    }

    const int SMEM_POST = (512 * 36 + 32 * 68 + 2 * 544) * 4;
    cudaFuncSetAttribute(k_post, cudaFuncAttributeMaxDynamicSharedMemorySize, SMEM_POST);

    // fork side stream off the capture stream
    cudaEventRecord(evFork, 0);
    cudaStreamWaitEvent(s2, evFork, 0);

    // main stream: CSR build chain
    k_hist<<<(EE + 255) / 256, 256>>>(edst);
    // side stream: attn fold + input GEMM (independent of CSR)
    k_fold<<<1, 512, 0, s2>>>(W1, al1, ar1, W2, al2, ar2);
    k_part<<<NB79, 256>>>();
    k_in<<<NN / 16, 128, 0, s2>>>(g, W_in, b_in);   // profiled slot (idx 3)
    k_addoff2<<<NB79, 256>>>();
    k_scatter<<<(EE + 255) / 256, 256>>>(esrc, edst);

    // join
    cudaEventRecord(evJoin, s2);
    cudaStreamWaitEvent(0, evJoin, 0);

    k_agg2_l0<<<NN / 8, 256>>>();
    k_post<<<NN / 32, 256, SMEM_POST>>>(W1, bias1);

    k_agg2_l1<<<NN / 8, 256>>>(gid);
    k_head<<<1, 512>>>(W2, bias2, Wh, bh, out);
}

// round 14
// speedup vs baseline: 1.2948x; 1.2948x over previous
#include <cuda_runtime.h>

#define NN   20000
#define EE   320000
#define DIND 128
#define DH   64
#define H    8
#define B    16
#define C    10
#define NB79 ((NN + 255) / 256)
#define CAP2 64

// ---------------- packed f32x2 helpers ----------------------------------------
__device__ __forceinline__ unsigned long long pack2(float x, float y) {
    unsigned long long u;
    asm("mov.b64 %0, {%1,%2};" : "=l"(u) : "f"(x), "f"(y));
    return u;
}
__device__ __forceinline__ void unpack2(unsigned long long u, float& x, float& y) {
    asm("mov.b64 {%0,%1}, %2;" : "=f"(x), "=f"(y) : "l"(u));
}
__device__ __forceinline__ unsigned long long fma2(unsigned long long a,
                                                   unsigned long long b,
                                                   unsigned long long c) {
    unsigned long long d;
    asm("fma.rn.f32x2 %0, %1, %2, %3;" : "=l"(d) : "l"(a), "l"(b), "l"(c));
    return d;
}

// ---------------- scratch (static device globals; zero-init at load) -----------
__device__ float d_h0[NN * DH];
__device__ float d_agg[NN * H * DH];   // layer-0 aggregates only
__device__ float d_el[NN * H];         // layer-1 logits (k_in)
__device__ float d_er[NN * H];
__device__ float d_el2[NN * H];        // layer-2 logits (k_post)
__device__ float d_er2[NN * H];
__device__ float d_hmid[NN * DH];
__device__ float d_wl1[H * DH], d_wr1[H * DH], d_wl2[H * DH], d_wr2[H * DH];
__device__ int   d_deg[NN];            // zeroed by k_agg2_l1 of previous replay
__device__ int   d_rowptr[NN + 1];
__device__ int   d_wpos[NN];           // (re)written by k_addoff2 every replay
__device__ int   d_col[EE];
__device__ int   d_part[NB79];
__device__ float d_gsum2[B * 512];     // per-graph agg sums; zeroed by k_head
__device__ float d_gcnt[B];            // zeroed by k_head

// ---------------- histogram of incoming degree ----------------------------------
__global__ void k_hist(const int* __restrict__ edst) {
    int e = blockIdx.x * 256 + threadIdx.x;
    if (e < EE) atomicAdd(&d_deg[edst[e]], 1);
}

// ---------------- fold attn vectors through W (single block, side stream) ------
__global__ void k_fold(const float* __restrict__ W1, const float* __restrict__ al1,
                       const float* __restrict__ ar1,
                       const float* __restrict__ W2, const float* __restrict__ al2,
                       const float* __restrict__ ar2) {
    int t = threadIdx.x;
    int h = t >> 6, k = t & 63;
    float l1 = 0.f, r1 = 0.f, l2 = 0.f, r2 = 0.f;
    for (int d = 0; d < DH; d++) {
        float w1 = W1[k * 512 + h * 64 + d];
        float w2 = W2[k * 512 + h * 64 + d];
        l1 += w1 * al1[h * 64 + d];
        r1 += w1 * ar1[h * 64 + d];
        l2 += w2 * al2[h * 64 + d];
        r2 += w2 * ar2[h * 64 + d];
    }
    d_wl1[t] = l1; d_wr1[t] = r1;
    d_wl2[t] = l2; d_wr2[t] = r2;
}

__global__ void k_part() {
    __shared__ int ws[8];
    int i = blockIdx.x * 256 + threadIdx.x;
    int v = (i < NN) ? d_deg[i] : 0;
#pragma unroll
    for (int o = 16; o; o >>= 1) v += __shfl_xor_sync(0xffffffffu, v, o);
    if ((threadIdx.x & 31) == 0) ws[threadIdx.x >> 5] = v;
    __syncthreads();
    if (threadIdx.x == 0) {
        int s = 0;
#pragma unroll
        for (int w = 0; w < 8; w++) s += ws[w];
        d_part[blockIdx.x] = s;
    }
}

// rowptr + row-start (into wpos); partial-scan of 79 block sums per block
__global__ void k_addoff2() {
    __shared__ int parts[NB79];
    __shared__ int ws[8];
    int t = threadIdx.x;
    int lane = t & 31, wid = t >> 5;
    if (t < NB79) parts[t] = d_part[t];
    __syncthreads();
    if (t == 0) {
        int run = 0;
        for (int i = 0; i < NB79; i++) { int v = parts[i]; parts[i] = run; run += v; }
    }
    __syncthreads();
    int i = blockIdx.x * 256 + t;
    int v0 = (i < NN) ? d_deg[i] : 0;
    int v = v0;
#pragma unroll
    for (int o = 1; o < 32; o <<= 1) {
        int x = __shfl_up_sync(0xffffffffu, v, o);
        if (lane >= o) v += x;
    }
    if (lane == 31) ws[wid] = v;
    __syncthreads();
    int woff = 0;
#pragma unroll
    for (int w = 0; w < 8; w++) woff += (w < wid) ? ws[w] : 0;
    if (i < NN) {
        int endp = parts[blockIdx.x] + woff + v;
        d_rowptr[i + 1] = endp;
        d_wpos[i] = endp - v0;
    }
    if (i == 0) d_rowptr[0] = 0;
}

__global__ void k_scatter(const int* __restrict__ esrc, const int* __restrict__ edst) {
    int e = blockIdx.x * 256 + threadIdx.x;
    if (e < EE) {
        int p = atomicAdd(&d_wpos[edst[e]], 1);
        d_col[p] = esrc[e];
    }
}

// ------- h0 = g@W_in + b (16 nodes, 128 threads) + fused layer-1 el/er ---------
__global__ __launch_bounds__(128) void k_in(const float* __restrict__ g,
                                            const float* __restrict__ W,
                                            const float* __restrict__ b) {
    __shared__ float sh_t[DIND * 20];
    __shared__ float s_h[16 * 68];
    __shared__ float s_w[2 * 544];
    int n0 = blockIdx.x * 16;
    int t = threadIdx.x;
#pragma unroll
    for (int r = 0; r < 4; r++) {
        int idx = t + 128 * r;
        int h = idx >> 6, d = idx & 63;
        s_w[h * 68 + d]       = d_wl1[idx];
        s_w[544 + h * 68 + d] = d_wr1[idx];
    }
#pragma unroll
    for (int r = 0; r < 16; r++) {
        int idx = t + 128 * r;
        int i = idx >> 7, k = idx & 127;
        sh_t[k * 20 + i] = g[(size_t)(n0 + i) * DIND + k];
    }
    __syncthreads();
    int col = t & 63, grp = t >> 6;
    unsigned long long acc[4] = {0ull, 0ull, 0ull, 0ull};
    for (int k = 0; k < DIND; k++) {
        float w = W[k * DH + col];
        unsigned long long ww = pack2(w, w);
        const ulonglong2* p = (const ulonglong2*)&sh_t[k * 20 + 8 * grp];
        ulonglong2 v0 = p[0], v1 = p[1];
        acc[0] = fma2(v0.x, ww, acc[0]);
        acc[1] = fma2(v0.y, ww, acc[1]);
        acc[2] = fma2(v1.x, ww, acc[2]);
        acc[3] = fma2(v1.y, ww, acc[3]);
    }
    float bb = b[col];
#pragma unroll
    for (int j = 0; j < 4; j++) {
        float x, y;
        unpack2(acc[j], x, y);
        x += bb; y += bb;
        int nd = 8 * grp + 2 * j;
        d_h0[(size_t)(n0 + nd) * DH + col]     = x;
        d_h0[(size_t)(n0 + nd + 1) * DH + col] = y;
        s_h[nd * 68 + col]       = x;
        s_h[(nd + 1) * 68 + col] = y;
    }
    __syncthreads();
    {
        int n = t >> 3, h = t & 7;
        const float4* sh4 = (const float4*)(s_h + n * 68);
        const float4* wl4 = (const float4*)(s_w + h * 68);
        const float4* wr4 = (const float4*)(s_w + 544 + h * 68);
        float el = 0.f, er = 0.f;
#pragma unroll
        for (int dd = 0; dd < 16; dd++) {
            float4 hv = sh4[dd];
            float4 a = wl4[dd];
            float4 r = wr4[dd];
            el += hv.x * a.x + hv.y * a.y + hv.z * a.z + hv.w * a.w;
            er += hv.x * r.x + hv.y * r.y + hv.z * r.z + hv.w * r.w;
        }
        d_el[(n0 + n) * 8 + h] = el;
        d_er[(n0 + n) * 8 + h] = er;
    }
}

// ===== shared body: softmax + 8-head gather; acc returned in registers =========
__device__ __forceinline__ void agg_body(
    const float* __restrict__ hin, const float* __restrict__ elp,
    const float* __restrict__ erp,
    float (*s_alpha)[CAP2][8], int (*s_col)[CAP2],
    float (*s_m)[8], float (*s_inv)[8], float (*s_er)[8],
    int w, int lane, int n, int base, int deg, int dcap,
    unsigned long long acc[8]) {
    for (int k = lane; k < dcap; k += 32) s_col[w][k] = d_col[base + k];
    __syncwarp();

    int h = lane & 7, slot8 = lane >> 3;
    float er_h = erp[n * 8 + h];
#pragma unroll 4
    for (int k = slot8; k < dcap; k += 4) {
        int s = s_col[w][k];
        float e = elp[s * 8 + h] + er_h;
        e = e > 0.f ? e : 0.2f * e;
        s_alpha[w][k][h] = e;
    }
    float mo = -1e30f, sso = 0.f;                // overflow region (rare)
    for (int k = CAP2 + slot8; k < deg; k += 4) {
        int s = d_col[base + k];
        float e = elp[s * 8 + h] + er_h;
        e = e > 0.f ? e : 0.2f * e;
        float nm = fmaxf(mo, e);
        sso = sso * __expf(mo - nm) + __expf(e - nm);
        mo = nm;
    }
    __syncwarp();

    float m = mo;
    for (int k = slot8; k < dcap; k += 4) m = fmaxf(m, s_alpha[w][k][h]);
#pragma unroll
    for (int o = 8; o <= 16; o <<= 1) m = fmaxf(m, __shfl_xor_sync(0xffffffffu, m, o));
    float ss = sso * __expf(mo - m);
    for (int k = slot8; k < dcap; k += 4) ss += __expf(s_alpha[w][k][h] - m);
#pragma unroll
    for (int o = 8; o <= 16; o <<= 1) ss += __shfl_xor_sync(0xffffffffu, ss, o);
    float inv = 1.f / ss;
    if (lane < 8) { s_m[w][h] = m; s_inv[w][h] = inv; s_er[w][h] = er_h; }

    for (int k = slot8; k < dcap; k += 4)
        s_alpha[w][k][h] = __expf(s_alpha[w][k][h] - m) * inv;
    __syncwarp();

#pragma unroll
    for (int j = 0; j < 8; j++) acc[j] = 0ull;
    const float* hb = hin + 2 * lane;
#pragma unroll 4
    for (int k = 0; k < dcap; k++) {
        int s = s_col[w][k];
        unsigned long long f = *(const unsigned long long*)(hb + (size_t)s * 64);
        const float4* ap = (const float4*)&s_alpha[w][k][0];
        float4 a0 = ap[0], a1 = ap[1];
        acc[0] = fma2(f, pack2(a0.x, a0.x), acc[0]);
        acc[1] = fma2(f, pack2(a0.y, a0.y), acc[1]);
        acc[2] = fma2(f, pack2(a0.z, a0.z), acc[2]);
        acc[3] = fma2(f, pack2(a0.w, a0.w), acc[3]);
        acc[4] = fma2(f, pack2(a1.x, a1.x), acc[4]);
        acc[5] = fma2(f, pack2(a1.y, a1.y), acc[5]);
        acc[6] = fma2(f, pack2(a1.z, a1.z), acc[6]);
        acc[7] = fma2(f, pack2(a1.w, a1.w), acc[7]);
    }
    if (deg > CAP2) {
        for (int k = CAP2; k < deg; k++) {
            int s = d_col[base + k];
            unsigned long long f = *(const unsigned long long*)(hb + (size_t)s * 64);
#pragma unroll
            for (int hh = 0; hh < 8; hh++) {
                float e = elp[s * 8 + hh] + s_er[w][hh];
                e = e > 0.f ? e : 0.2f * e;
                float a = __expf(e - s_m[w][hh]) * s_inv[w][hh];
                acc[hh] = fma2(f, pack2(a, a), acc[hh]);
            }
        }
    }
}

// ------- layer-0 aggregation: write per-node aggregate to d_agg ----------------
__global__ __launch_bounds__(256) void k_agg2_l0() {
    __shared__ float s_alpha[8][CAP2][8];
    __shared__ int   s_col[8][CAP2];
    __shared__ float s_m[8][8], s_inv[8][8], s_er[8][8];
    int w = threadIdx.x >> 5, lane = threadIdx.x & 31;
    int n = blockIdx.x * 8 + w;
    int base = d_rowptr[n];
    int deg  = d_rowptr[n + 1] - base;
    int dcap = min(deg, CAP2);
    unsigned long long acc[8];
    agg_body(d_h0, d_el, d_er, s_alpha, s_col, s_m, s_inv, s_er,
             w, lane, n, base, deg, dcap, acc);
    float* ob = d_agg + (size_t)n * 512 + 2 * lane;
#pragma unroll
    for (int hh = 0; hh < 8; hh++)
        *(unsigned long long*)(ob + hh * 64) = acc[hh];
}

// ------- layer-1 aggregation + per-graph reduction (atomic-free smem) ----------
__global__ __launch_bounds__(256) void k_agg2_l1(const int* __restrict__ gid) {
    __shared__ float s_alpha[8][CAP2][8];      // 4096 floats; reused as accum
    __shared__ int   s_col[8][CAP2];
    __shared__ float s_m[8][8], s_inv[8][8], s_er[8][8];
    __shared__ int   s_gid[8];
    float* accum = &s_alpha[0][0][0];
    int t = threadIdx.x;
    int w = t >> 5, lane = t & 31;
    int n = blockIdx.x * 8 + w;
    int base = d_rowptr[n];
    int deg  = d_rowptr[n + 1] - base;
    int dcap = min(deg, CAP2);
    unsigned long long acc[8];
    agg_body(d_hmid, d_el2, d_er2, s_alpha, s_col, s_m, s_inv, s_er,
             w, lane, n, base, deg, dcap, acc);

    __syncthreads();                              // everyone done with s_alpha
#pragma unroll
    for (int hh = 0; hh < 8; hh++)
        *(unsigned long long*)&accum[w * 512 + hh * 64 + 2 * lane] = acc[hh];
    if (t < 8) {
        s_gid[t] = gid[blockIdx.x * 8 + t];
        atomicAdd(&d_gcnt[s_gid[t]], 1.f);
        d_deg[blockIdx.x * 8 + t] = 0;            // clean for replay
    }
    __syncthreads();
    int gfirst = s_gid[0], glast = s_gid[7];
    if (gfirst == glast) {                        // common case: one graph
#pragma unroll
        for (int q = 0; q < 2; q++) {
            int d = t + 256 * q;
            float s = 0.f;
#pragma unroll
            for (int ww = 0; ww < 8; ww++) s += accum[ww * 512 + d];
            atomicAdd(&d_gsum2[gfirst * 512 + d], s);
        }
    } else {                                      // boundary block: <=8 graphs
#pragma unroll
        for (int q = 0; q < 2; q++) {
            int d = t + 256 * q;
            for (int gg = gfirst; gg <= glast; gg++) {
                float s = 0.f;
                bool any = false;
#pragma unroll
                for (int ww = 0; ww < 8; ww++)
                    if (s_gid[ww] == gg) { s += accum[ww * 512 + d]; any = true; }
                if (any) atomicAdd(&d_gsum2[gg * 512 + d], s);
            }
        }
    }
}

// ------- post (layer 0 only): per-head GEMM + bias + relu + head-mean ----------
// + fused layer-2 el/er. thread = 4 cols x 16 nodes.
__global__ __launch_bounds__(256, 2) void k_post(const float* __restrict__ W,
                                                 const float* __restrict__ bias) {
    extern __shared__ float sm[];
    float* aggT = sm;                           // [512][36] staging, later [32][512]
    float* s_h  = sm + 512 * 36;                // [32][68]
    float* s_w  = s_h + 32 * 68;                // wl2|wr2 (rows padded to 68)
    int n0 = blockIdx.x * 32;
    int t = threadIdx.x;
    {
        int h = t >> 6, d = t & 63;
        s_w[h * 68 + d]           = d_wl2[t];
        s_w[544 + h * 68 + d]     = d_wr2[t];
        int t2 = t + 256, h2 = t2 >> 6, d2 = t2 & 63;
        s_w[h2 * 68 + d2]         = d_wl2[t2];
        s_w[544 + h2 * 68 + d2]   = d_wr2[t2];
    }
#pragma unroll
    for (int r = 0; r < 64; r++) {
        int idx = t + 256 * r;                   // 16384 elements
        int i = idx >> 9, j = idx & 511;
        aggT[j * 36 + i] = d_agg[(size_t)(n0 + i) * 512 + j];
    }
    __syncthreads();
    int cg = t & 127, half = t >> 7;             // cols 4cg..4cg+3; nodes 16half..+15
    int h = cg >> 4;
    int colb = 4 * cg;
    unsigned long long acc[32];
#pragma unroll
    for (int j = 0; j < 32; j++) acc[j] = 0ull;
    const float4* W4 = (const float4*)W;
    for (int k = 0; k < DH; k++) {
        float4 wv = W4[k * 128 + cg];
        unsigned long long ww0 = pack2(wv.x, wv.x);
        unsigned long long ww1 = pack2(wv.y, wv.y);
        unsigned long long ww2 = pack2(wv.z, wv.z);
        unsigned long long ww3 = pack2(wv.w, wv.w);
        const ulonglong2* p = (const ulonglong2*)&aggT[(h * 64 + k) * 36 + 16 * half];
#pragma unroll
        for (int j = 0; j < 4; j++) {
            ulonglong2 v = p[j];
            acc[(2 * j) * 4 + 0]     = fma2(v.x, ww0, acc[(2 * j) * 4 + 0]);
            acc[(2 * j) * 4 + 1]     = fma2(v.x, ww1, acc[(2 * j) * 4 + 1]);
            acc[(2 * j) * 4 + 2]     = fma2(v.x, ww2, acc[(2 * j) * 4 + 2]);
            acc[(2 * j) * 4 + 3]     = fma2(v.x, ww3, acc[(2 * j) * 4 + 3]);
            acc[(2 * j + 1) * 4 + 0] = fma2(v.y, ww0, acc[(2 * j + 1) * 4 + 0]);
            acc[(2 * j + 1) * 4 + 1] = fma2(v.y, ww1, acc[(2 * j + 1) * 4 + 1]);
            acc[(2 * j + 1) * 4 + 2] = fma2(v.y, ww2, acc[(2 * j + 1) * 4 + 2]);
            acc[(2 * j + 1) * 4 + 3] = fma2(v.y, ww3, acc[(2 * j + 1) * 4 + 3]);
        }
    }
    __syncthreads();                             // aggT reused as output buffer
    float4 bb = ((const float4*)bias)[cg];
#pragma unroll
    for (int q = 0; q < 8; q++) {
        float x0, y0, x1, y1, x2, y2, x3, y3;
        unpack2(acc[q * 4 + 0], x0, y0);
        unpack2(acc[q * 4 + 1], x1, y1);
        unpack2(acc[q * 4 + 2], x2, y2);
        unpack2(acc[q * 4 + 3], x3, y3);
        int node = 16 * half + 2 * q;
        float4 vx = make_float4(x0 + bb.x, x1 + bb.y, x2 + bb.z, x3 + bb.w);
        float4 vy = make_float4(y0 + bb.x, y1 + bb.y, y2 + bb.z, y3 + bb.w);
        *(float4*)&aggT[node * 512 + colb]       = vx;
        *(float4*)&aggT[(node + 1) * 512 + colb] = vy;
    }
    __syncthreads();
#pragma unroll
    for (int r = 0; r < 8; r++) {
        int idx = t + 256 * r;                   // 2048 = 32 nodes x 64 dims
        int i = idx >> 6, d = idx & 63;
        float v = 0.f;
#pragma unroll
        for (int hh = 0; hh < 8; hh++) v += aggT[i * 512 + hh * 64 + d];
        v = fmaxf(v * 0.125f, 0.f);
        d_hmid[(size_t)(n0 + i) * DH + d] = v;
        s_h[i * 68 + d] = v;
    }
    __syncthreads();
    {                                            // 32 nodes x 8 heads = 256 threads
        int nn = t >> 3, h2 = t & 7;
        const float4* sh4 = (const float4*)(s_h + nn * 68);
        const float4* wl4 = (const float4*)(s_w + h2 * 68);
        const float4* wr4 = (const float4*)(s_w + 544 + h2 * 68);
        float el = 0.f, er = 0.f;
#pragma unroll
        for (int dd = 0; dd < 16; dd++) {
            float4 hv = sh4[dd];
            float4 a = wl4[dd];
            float4 r = wr4[dd];
            el += hv.x * a.x + hv.y * a.y + hv.z * a.z + hv.w * a.w;
            er += hv.x * r.x + hv.y * r.y + hv.z * r.z + hv.w * r.w;
        }
        d_el2[(n0 + nn) * 8 + h2] = el;
        d_er2[(n0 + nn) * 8 + h2] = er;
    }
}

// ------- head: one block PER GRAPH; coalesced W2 loads; folded layer-2 linear --
__global__ __launch_bounds__(512) void k_head(const float* __restrict__ W2,
                                              const float* __restrict__ bias2,
                                              const float* __restrict__ Wh,
                                              const float* __restrict__ bh,
                                              float* __restrict__ out) {
    __shared__ float s_g[512];
    __shared__ float s_part[512];
    __shared__ float s_hg[64];
    __shared__ float s_lg[C];
    int g = blockIdx.x;
    int t = threadIdx.x;
    s_g[t] = d_gsum2[g * 512 + t];
    __syncthreads();
    float cnt = d_gcnt[g];
    int h = t >> 6, d = t & 63;
    const float* gv = s_g + h * 64;
    const float* wp = W2 + h * 64 + d;           // lanes sweep d -> coalesced
    float acc = 0.f;
#pragma unroll 16
    for (int k = 0; k < 64; k++) acc += gv[k] * wp[k * 512];
    s_part[t] = acc;
    __syncthreads();
    if (t < 64) {
        float s = 0.f;
#pragma unroll
        for (int hh = 0; hh < 8; hh++) s += s_part[hh * 64 + t];
        float bm = 0.f;
#pragma unroll
        for (int hh = 0; hh < 8; hh++) bm += bias2[hh * 64 + t];
        s_hg[t] = (cnt > 0.f) ? (s / (8.f * cnt) + bm * 0.125f) : 0.f;
    }
    __syncthreads();
    if (t < C) {
        float a = 0.f;
#pragma unroll 16
        for (int d2 = 0; d2 < 64; d2++) a += s_hg[d2] * Wh[d2 * C + t];
        s_lg[t] = a + bh[t];
    }
    __syncthreads();
    if (t == 0) {
        float mx = -1e30f;
#pragma unroll
        for (int c = 0; c < C; c++) mx = fmaxf(mx, s_lg[c]);
        float ssum = 0.f;
        float e[C];
#pragma unroll
        for (int c = 0; c < C; c++) { e[c] = expf(s_lg[c] - mx); ssum += e[c]; }
#pragma unroll
        for (int c = 0; c < C; c++) out[g * C + c] = e[c] / ssum;
    }
    d_gsum2[g * 512 + t] = 0.f;                  // clean own slice for replay
    if (t == 0) d_gcnt[g] = 0.f;
}

// ---------------- launch (two-stream fork: CSR build || input GEMM) ------------
extern "C" void kernel_launch(void* const* d_in, const int* in_sizes, int n_in,
                              void* d_out, int out_size) {
    const float* g    = (const float*)d_in[0];
    const int*   esrc = (const int*)d_in[1];
    const int*   edst = (const int*)d_in[2];
    const int*   gid  = (const int*)d_in[3];
    const float* W_in = (const float*)d_in[4];
    const float* b_in = (const float*)d_in[5];
    const float* W1   = (const float*)d_in[6];
    const float* al1  = (const float*)d_in[7];
    const float* ar1  = (const float*)d_in[8];
    const float* bias1= (const float*)d_in[9];
    const float* W2   = (const float*)d_in[10];
    const float* al2  = (const float*)d_in[11];
    const float* ar2  = (const float*)d_in[12];
    const float* bias2= (const float*)d_in[13];
    const float* Wh   = (const float*)d_in[14];
    const float* bh   = (const float*)d_in[15];
    float* out = (float*)d_out;

    static cudaStream_t s2 = nullptr;
    static cudaEvent_t evFork = nullptr, evJoin = nullptr;
    if (s2 == nullptr) {
        cudaStreamCreateWithFlags(&s2, cudaStreamNonBlocking);
        cudaEventCreateWithFlags(&evFork, cudaEventDisableTiming);
        cudaEventCreateWithFlags(&evJoin, cudaEventDisableTiming);
    }

    const int SMEM_POST = (512 * 36 + 32 * 68 + 2 * 544) * 4;
    cudaFuncSetAttribute(k_post, cudaFuncAttributeMaxDynamicSharedMemorySize, SMEM_POST);

    // fork side stream off the capture stream
    cudaEventRecord(evFork, 0);
    cudaStreamWaitEvent(s2, evFork, 0);

    // main stream: CSR build chain
    k_hist<<<(EE + 255) / 256, 256>>>(edst);
    // side stream: attn fold + input GEMM (independent of CSR)
    k_fold<<<1, 512, 0, s2>>>(W1, al1, ar1, W2, al2, ar2);
    k_part<<<NB79, 256>>>();
    k_in<<<NN / 16, 128, 0, s2>>>(g, W_in, b_in);   // profiled slot (idx 3)
    k_addoff2<<<NB79, 256>>>();
    k_scatter<<<(EE + 255) / 256, 256>>>(esrc, edst);

    // join
    cudaEventRecord(evJoin, s2);
    cudaStreamWaitEvent(0, evJoin, 0);

    k_agg2_l0<<<NN / 8, 256>>>();
    k_post<<<NN / 32, 256, SMEM_POST>>>(W1, bias1);

    k_agg2_l1<<<NN / 8, 256>>>(gid);
    k_head<<<B, 512>>>(W2, bias2, Wh, bh, out);
}